// round 2
// baseline (speedup 1.0000x reference)
#include <cuda_runtime.h>
#include <math.h>

// ---------------- static device scratch (no allocations allowed) ----------------
#define HW   65536      // 256*256
#define NIMG 16

__device__ float    g_yiq   [2u*NIMG*3*HW];    // [c in {x,y}][n][ch][pix] natural layout
__device__ float2   g_fftin [2u*NIMG*HW];      // Y*255 as complex
__device__ float2   g_Xspec [2u*NIMG*HW];      // forward FFT result
__device__ float2   g_tmp   [512u*HW];         // ping buffer (fwd scratch + filtered row-FFT)
__device__ float    g_filt  [16u*HW];          // [f=s*4+o][pix]
__device__ float    g_energy[2u*NIMG*4*HW];    // [cn][o][pix'] (TRANSPOSED pix' = w*256+h)
__device__ unsigned g_e2    [2u*NIMG*4*HW];    // float bits of |Eo_s0|^2 (order-free use)
__device__ float    g_amp   [2u*NIMG*HW];      // [cn][pix'] transposed
__device__ float    g_pc    [2u*NIMG*HW];      // [cn][pix] NATURAL layout
__device__ float    g_em    [4];
__device__ float    g_aiaj  [4];
__device__ float    g_thr   [2*NIMG*4];
__device__ float    g_part  [2*4096];          // per-block num / den partials

static __device__ __forceinline__ float2 cmulf(float2 a, float2 b) {
    return make_float2(a.x*b.x - a.y*b.y, a.x*b.y + a.y*b.x);
}

// ---------------- preprocess: 2x2 mean pool + RGB->YIQ + FFT input ----------------
__global__ void k_preprocess(const float* __restrict__ x, const float* __restrict__ y)
{
    int idx = blockIdx.x * 256 + threadIdx.x;          // 2*16*65536
    int cn  = idx >> 16;
    int pix = idx & 65535;
    int c = cn >> 4, n = cn & 15;
    int h = pix >> 8, w = pix & 255;
    const float* src = (c == 0 ? x : y) + (size_t)n * 3 * 262144;
    float rgb[3];
    #pragma unroll
    for (int ch = 0; ch < 3; ++ch) {
        const float* p = src + (size_t)ch * 262144 + (size_t)(2*h) * 512 + 2*w;
        rgb[ch] = 0.25f * (p[0] + p[1] + p[512] + p[513]);
    }
    float Y = 0.299f *rgb[0] + 0.587f *rgb[1] + 0.114f *rgb[2];
    float I = 0.5969f*rgb[0] - 0.2746f*rgb[1] - 0.3213f*rgb[2];
    float Q = 0.2115f*rgb[0] - 0.5227f*rgb[1] + 0.3112f*rgb[2];
    size_t base = (size_t)cn * 3 * HW;
    g_yiq[base + pix]            = Y;
    g_yiq[base + HW + pix]       = I;
    g_yiq[base + 2u*HW + pix]    = Q;
    g_fftin[(size_t)cn * HW + pix] = make_float2(Y * 255.0f, 0.0f);
}

// ---------------- log-Gabor filters (frequency domain) ----------------
__global__ void k_filters()
{
    int pix = blockIdx.x * 256 + threadIdx.x;
    int i = pix >> 8, j = pix & 255;
    float u = (float)(i < 128 ? i : i - 256) * (1.0f/256.0f);
    float v = (float)(j < 128 ? j : j - 256) * (1.0f/256.0f);
    float r = sqrtf(u*u + v*v);
    float theta = atan2f(-v, u);
    float lp = 1.0f / (1.0f + powf(r * (1.0f/0.45f), 30.0f));
    float rs = (pix == 0) ? 1.0f : r;
    float ct = cosf(theta), st = sinf(theta);
    float bo[4];
    #pragma unroll
    for (int o = 0; o < 4; ++o) {
        float thj = 0.7853981633974483f * (float)o;  // pi*o/4
        float cj = cosf(thj), sj = sinf(thj);
        float ds = st*cj - ct*sj;
        float dc = ct*cj + st*sj;
        float dt = atan2f(ds, dc);
        bo[o] = expf(-dt*dt / 0.85674050f);          // 2*sigma_theta^2
    }
    #pragma unroll
    for (int s = 0; s < 4; ++s) {
        float f0 = 1.0f / (6.0f * (float)(1 << s));
        float lr = logf(rs / f0);
        float a = expf(-lr*lr / 0.52941847f) * lp;   // 2*ln(sigma_f)^2
        if (pix == 0) a = 0.0f;
        #pragma unroll
        for (int o = 0; o < 4; ++o)
            g_filt[(size_t)(s*4 + o) * HW + pix] = a * bo[o];
    }
}

// em[o] = sum filt[s=0,o]^2 ; sum_aiaj[o] = sum_k ((F(k)+F(-k))/2)^2, F = sum_s filt
// (Parseval on the Hermitian part: Re(ifft(F)) = ifft((F(k)+F(-k))/2) for real F)
__global__ void k_filter_stats()
{
    int o = blockIdx.x;
    int tid = threadIdx.x;
    float em_acc = 0.0f, aj_acc = 0.0f;
    for (int pix = tid; pix < HW; pix += 256) {
        int i = pix >> 8, j = pix & 255;
        int npix = (((256 - i) & 255) << 8) | ((256 - j) & 255);
        float f0 = g_filt[(size_t)o * HW + pix];
        em_acc += f0 * f0;
        float F  = f0
                 + g_filt[(size_t)(4  + o) * HW + pix]
                 + g_filt[(size_t)(8  + o) * HW + pix]
                 + g_filt[(size_t)(12 + o) * HW + pix];
        float Fn = g_filt[(size_t)(o)      * HW + npix]
                 + g_filt[(size_t)(4  + o) * HW + npix]
                 + g_filt[(size_t)(8  + o) * HW + npix]
                 + g_filt[(size_t)(12 + o) * HW + npix];
        float hh = 0.5f * (F + Fn);
        aj_acc += hh * hh;
    }
    __shared__ float se[256], sa[256];
    se[tid] = em_acc; sa[tid] = aj_acc;
    __syncthreads();
    for (int s = 128; s > 0; s >>= 1) {
        if (tid < s) { se[tid] += se[tid + s]; sa[tid] += sa[tid + s]; }
        __syncthreads();
    }
    if (tid == 0) { g_em[o] = se[0]; g_aiaj[o] = sa[0]; }
}

// ---------------- batched 256-pt Stockham FFT pass (transposed store) --------------
// sel: 0 fwd p1 (fftin->tmp), 1 fwd p2 (tmp->Xspec), 2 inv p1 with filter mul
//      (Xspec*filt->tmp, scaled 1/256)
__global__ void __launch_bounds__(512) fft_pass(int sel, float scale)
{
    __shared__ float2 bufA[4][257];
    __shared__ float2 bufB[4][257];
    __shared__ float2 tw[128];
    int tid  = threadIdx.x;         // 0..511
    int line = tid >> 7;            // 0..3
    int t    = tid & 127;
    int b    = blockIdx.x >> 6;     // batch index
    int r0   = (blockIdx.x & 63) << 2;
    bool inv = (sel >= 2);

    if (tid < 128) {
        float ang = (inv ? 6.2831853071795864769f : -6.2831853071795864769f)
                    * (float)tid * (1.0f/256.0f);
        float s_, c_; sincosf(ang, &s_, &c_);
        tw[tid] = make_float2(c_, s_);
    }

    const size_t lineoff = (size_t)r0 * 256;
    if (sel == 0) {
        const float2* s = g_fftin + (size_t)b * HW + lineoff;
        for (int i = tid; i < 1024; i += 512) bufA[i >> 8][i & 255] = s[i];
    } else if (sel == 1) {
        const float2* s = g_tmp + (size_t)b * HW + lineoff;
        for (int i = tid; i < 1024; i += 512) bufA[i >> 8][i & 255] = s[i];
    } else {
        const float2* s  = g_Xspec + (size_t)(b >> 4) * HW + lineoff;
        const float*  fp = g_filt  + (size_t)(b & 15) * HW + lineoff;
        for (int i = tid; i < 1024; i += 512) {
            float2 v = s[i]; float g = fp[i];
            bufA[i >> 8][i & 255] = make_float2(v.x * g, v.y * g);
        }
    }
    __syncthreads();

    float2* xp = bufA[line];
    float2* yp = bufB[line];
    #pragma unroll
    for (int st = 0; st < 8; ++st) {
        float2 c0 = xp[t];
        float2 c1 = xp[t + 128];
        int j = t >> st;
        int k = t & ((1 << st) - 1);
        float2 w  = tw[j << st];
        float2 su = make_float2(c0.x + c1.x, c0.y + c1.y);
        float2 di = make_float2(c0.x - c1.x, c0.y - c1.y);
        int ob = k + (j << (st + 1));
        yp[ob]             = su;
        yp[ob + (1 << st)] = cmulf(di, w);
        __syncthreads();
        float2* tp = xp; xp = yp; yp = tp;
    }
    // 8 swaps: result back in bufA

    float2* dp = (sel == 1) ? g_Xspec : g_tmp;
    dp += (size_t)b * HW;
    for (int i = tid; i < 1024; i += 512) {
        int w  = i >> 2, rl = i & 3;
        float2 v = bufA[rl][w];
        dp[(size_t)w * 256 + (r0 + rl)] = make_float2(v.x * scale, v.y * scale);
    }
}

// ---------------- FUSED: 2nd inverse-FFT pass + energy/amp/e2 ----------------
// grid: 2*NIMG (cn) * 64 (row groups), 512 threads. Each block runs the 16
// filter IFFT columns for its 4 lines, keeping Eo in registers (pixel layout
// transposed: pix' = w*256 + h).
__global__ void __launch_bounds__(512) k_ifft_energy()
{
    __shared__ float2 bufA[4][257];
    __shared__ float2 bufB[4][257];
    __shared__ float2 tw[128];
    int tid  = threadIdx.x;
    int line = tid >> 7;
    int t    = tid & 127;
    int cn   = blockIdx.x >> 6;
    int r0   = (blockIdx.x & 63) << 2;

    if (tid < 128) {
        float ang = 6.2831853071795864769f * (float)tid * (1.0f/256.0f);  // inverse
        float s_, c_; sincosf(ang, &s_, &c_);
        tw[tid] = make_float2(c_, s_);
    }

    // pixel assignments: thread handles elements tid and tid+512 of the 4x256 tile
    int h0  = tid & 255;
    int rl0 = tid >> 8;             // 0 or 1 (second pixel uses rl0+2)
    int pixp0 = (r0 + rl0) * 256 + h0;
    int pixp1 = (r0 + rl0 + 2) * 256 + h0;

    float amp0 = 0.0f, amp1 = 0.0f;

    #pragma unroll
    for (int o = 0; o < 4; ++o) {
        float er0[4], ei0[4], er1[4], ei1[4];
        #pragma unroll
        for (int s = 0; s < 4; ++s) {
            int f = s * 4 + o;
            const float2* src = g_tmp + ((size_t)(cn * 16 + f)) * HW + (size_t)r0 * 256;
            for (int i = tid; i < 1024; i += 512) bufA[i >> 8][i & 255] = src[i];
            __syncthreads();

            float2* xp = bufA[line];
            float2* yp = bufB[line];
            #pragma unroll
            for (int st = 0; st < 8; ++st) {
                float2 c0 = xp[t];
                float2 c1 = xp[t + 128];
                int j = t >> st;
                int k = t & ((1 << st) - 1);
                float2 w  = tw[j << st];
                float2 su = make_float2(c0.x + c1.x, c0.y + c1.y);
                float2 di = make_float2(c0.x - c1.x, c0.y - c1.y);
                int ob = k + (j << (st + 1));
                yp[ob]             = su;
                yp[ob + (1 << st)] = cmulf(di, w);
                __syncthreads();
                float2* tp = xp; xp = yp; yp = tp;
            }
            float2 v0 = bufA[rl0    ][h0];
            float2 v1 = bufA[rl0 + 2][h0];
            er0[s] = v0.x * (1.0f/256.0f); ei0[s] = v0.y * (1.0f/256.0f);
            er1[s] = v1.x * (1.0f/256.0f); ei1[s] = v1.y * (1.0f/256.0f);
            __syncthreads();   // before next load reuses bufA
        }

        // pixel 0
        {
            float sx = er0[0]+er0[1]+er0[2]+er0[3];
            float sy = ei0[0]+ei0[1]+ei0[2]+ei0[3];
            float invm = 1.0f / (sqrtf(sx*sx + sy*sy) + 1e-8f);
            float mr = sx * invm, mi = sy * invm;
            float en = 0.0f;
            #pragma unroll
            for (int s = 0; s < 4; ++s) {
                en += (er0[s]*mr + ei0[s]*mi) - fabsf(ei0[s]*mr - er0[s]*mi);
                amp0 += sqrtf(er0[s]*er0[s] + ei0[s]*ei0[s]);
            }
            g_energy[((size_t)cn*4 + o) * HW + pixp0] = en;
            g_e2   [((size_t)cn*4 + o) * HW + pixp0] =
                __float_as_uint(er0[0]*er0[0] + ei0[0]*ei0[0]);
        }
        // pixel 1
        {
            float sx = er1[0]+er1[1]+er1[2]+er1[3];
            float sy = ei1[0]+ei1[1]+ei1[2]+ei1[3];
            float invm = 1.0f / (sqrtf(sx*sx + sy*sy) + 1e-8f);
            float mr = sx * invm, mi = sy * invm;
            float en = 0.0f;
            #pragma unroll
            for (int s = 0; s < 4; ++s) {
                en += (er1[s]*mr + ei1[s]*mi) - fabsf(ei1[s]*mr - er1[s]*mi);
                amp1 += sqrtf(er1[s]*er1[s] + ei1[s]*ei1[s]);
            }
            g_energy[((size_t)cn*4 + o) * HW + pixp1] = en;
            g_e2   [((size_t)cn*4 + o) * HW + pixp1] =
                __float_as_uint(er1[0]*er1[0] + ei1[0]*ei1[0]);
        }
    }
    g_amp[(size_t)cn * HW + pixp0] = amp0;
    g_amp[(size_t)cn * HW + pixp1] = amp1;
}

// ---------------- exact median via byte-radix select (warp-aggregated) ----------------
__global__ void k_median()
{
    const unsigned* data = g_e2 + (size_t)blockIdx.x * HW;  // blockIdx = cn*4+o
    __shared__ unsigned hist[256];
    __shared__ unsigned s_prefix;
    __shared__ int s_rank;
    int tid  = threadIdx.x;
    int lane = tid & 31;
    if (tid == 0) { s_prefix = 0u; s_rank = 32767; }        // (HW-1)//2
    __syncthreads();
    for (int shift = 24; shift >= 0; shift -= 8) {
        hist[tid] = 0u;
        __syncthreads();
        unsigned prefix = s_prefix;
        unsigned himask = (shift == 24) ? 0u : (0xFFFFFFFFu << (shift + 8));
        for (int i = tid; i < HW; i += 256) {
            unsigned v = data[i];
            bool pred = ((v & himask) == prefix);
            unsigned bk = pred ? ((v >> shift) & 255u) : 256u;
            unsigned m  = __match_any_sync(0xffffffffu, bk);
            if (pred && (unsigned)(__ffs(m) - 1) == (unsigned)lane)
                atomicAdd(&hist[bk], (unsigned)__popc(m));
        }
        __syncthreads();
        if (tid == 0) {
            int r = s_rank; unsigned cum = 0; int bk = 0;
            for (; bk < 256; ++bk) {
                if (cum + hist[bk] > (unsigned)r) break;
                cum += hist[bk];
            }
            s_prefix = prefix | ((unsigned)bk << shift);
            s_rank   = r - (int)cum;
        }
        __syncthreads();
    }
    if (tid == 0) {
        int o = blockIdx.x & 3;
        float median  = __uint_as_float(s_prefix);
        float mean_e2 = median * 1.4426950408889634f;       // -median/ln(0.5)
        float tau = sqrtf(mean_e2 / g_em[o] * g_aiaj[o]);
        g_thr[blockIdx.x] = tau * 1.5079922765f;            // (c + 2d)/1.7
    }
}

// ---------------- pc map: read transposed, write natural (smem tile transpose) --------
__global__ void __launch_bounds__(1024) k_pc()
{
    __shared__ float sm[32][33];
    int cn   = blockIdx.x >> 6;
    int tile = blockIdx.x & 63;
    int w0 = (tile >> 3) << 5, h0 = (tile & 7) << 5;
    int r = threadIdx.x >> 5, c = threadIdx.x & 31;
    int pixp = (w0 + r) * 256 + (h0 + c);                   // coalesced in c
    float a = g_amp[(size_t)cn * HW + pixp];
    float acc = 0.0f;
    #pragma unroll
    for (int o = 0; o < 4; ++o)
        acc += fmaxf(g_energy[((size_t)cn*4 + o) * HW + pixp] - g_thr[cn*4 + o], 0.0f);
    sm[r][c] = acc / (a + 1e-8f);
    __syncthreads();
    // natural pixel (h0+r, w0+c) holds value sm[c][r]
    g_pc[(size_t)cn * HW + (h0 + r) * 256 + (w0 + c)] = sm[c][r];
}

// ---------------- FSIM pointwise + per-block reduction ----------------
__global__ void k_fsim_partial(const float* __restrict__ ker)
{
    const float T1 = 0.85f;
    const float T2 = 160.0f / 65025.0f;
    const float T3 = 200.0f / 65025.0f;
    const float T4 = 200.0f / 65025.0f;
    int tid = threadIdx.x;
    int n   = blockIdx.x >> 8;
    int pix = ((blockIdx.x & 255) << 8) | tid;
    int h = pix >> 8, w = pix & 255;

    const float* Yx = g_yiq + ((size_t)(0*NIMG + n) * 3 + 0) * HW;
    const float* Yy = g_yiq + ((size_t)(1*NIMG + n) * 3 + 0) * HW;

    float g0x = 0.f, g1x = 0.f, g0y = 0.f, g1y = 0.f;
    #pragma unroll
    for (int ky = 0; ky < 3; ++ky) {
        int hh = h + ky - 1;
        if (hh < 0 || hh > 255) continue;
        #pragma unroll
        for (int kx = 0; kx < 3; ++kx) {
            int ww = w + kx - 1;
            if (ww < 0 || ww > 255) continue;
            float vx = Yx[hh*256 + ww], vy = Yy[hh*256 + ww];
            float k0 = ker[ky*3 + kx], k1 = ker[9 + ky*3 + kx];
            g0x += k0*vx; g1x += k1*vx;
            g0y += k0*vy; g1y += k1*vy;
        }
    }
    float gX = sqrtf(g0x*g0x + g1x*g1x);
    float gY = sqrtf(g0y*g0y + g1y*g1y);

    float pcx = g_pc[(size_t)(0*NIMG + n) * HW + pix];
    float pcy = g_pc[(size_t)(1*NIMG + n) * HW + pix];
    float s_pc = (2.0f*pcx*pcy + T1) / (pcx*pcx + pcy*pcy + T1);
    float s_g  = (2.0f*gX*gY + T2) / (gX*gX + gY*gY + T2);

    float ix = g_yiq[((size_t)(0*NIMG + n) * 3 + 1) * HW + pix];
    float iy = g_yiq[((size_t)(1*NIMG + n) * 3 + 1) * HW + pix];
    float qx = g_yiq[((size_t)(0*NIMG + n) * 3 + 2) * HW + pix];
    float qy = g_yiq[((size_t)(1*NIMG + n) * 3 + 2) * HW + pix];
    float s_i = (2.0f*ix*iy + T3) / (ix*ix + iy*iy + T3);
    float s_q = (2.0f*qx*qy + T4) / (qx*qx + qy*qy + T4);
    float siq = s_i * s_q;
    float slam = powf(fabsf(siq), 0.03f) * (siq < 0.0f ? 0.99556196f : 1.0f); // cos(0.03*pi)

    float pcm = fmaxf(pcx, pcy);
    float num = s_pc * s_g * slam * pcm;
    float den = pcm;

    __shared__ float sn[256], sd[256];
    sn[tid] = num; sd[tid] = den;
    __syncthreads();
    for (int s = 128; s > 0; s >>= 1) {
        if (tid < s) { sn[tid] += sn[tid + s]; sd[tid] += sd[tid + s]; }
        __syncthreads();
    }
    if (tid == 0) {
        g_part[blockIdx.x]        = sn[0];
        g_part[4096 + blockIdx.x] = sd[0];
    }
}

__global__ void k_final(float* __restrict__ out)
{
    int tid = threadIdx.x;          // 512
    int n = tid >> 5, lane = tid & 31;
    float num = 0.f, den = 0.f;
    for (int i = lane; i < 256; i += 32) {
        num += g_part[n*256 + i];
        den += g_part[4096 + n*256 + i];
    }
    #pragma unroll
    for (int off = 16; off > 0; off >>= 1) {
        num += __shfl_down_sync(0xffffffffu, num, off);
        den += __shfl_down_sync(0xffffffffu, den, off);
    }
    __shared__ float fs[16];
    if (lane == 0) fs[n] = num / den;
    __syncthreads();
    if (tid == 0) {
        float s = 0.f;
        #pragma unroll
        for (int k = 0; k < 16; ++k) s += fs[k];
        out[0] = s * (1.0f / 16.0f);
    }
}

// ---------------- launch ----------------
extern "C" void kernel_launch(void* const* d_in, const int* in_sizes, int n_in,
                              void* d_out, int out_size)
{
    (void)in_sizes; (void)n_in; (void)out_size;
    const float* x   = (const float*)d_in[0];
    const float* y   = (const float*)d_in[1];
    const float* ker = (const float*)d_in[2];
    float* out = (float*)d_out;

    k_preprocess   <<<8192, 256>>>(x, y);
    k_filters      <<<256, 256>>>();
    k_filter_stats <<<4, 256>>>();
    fft_pass       <<<32*64, 512>>>(0, 1.0f);              // fwd rows
    fft_pass       <<<32*64, 512>>>(1, 1.0f);              // fwd cols
    fft_pass       <<<512*64, 512>>>(2, 1.0f/256.0f);      // inv rows (x filter)
    k_ifft_energy  <<<32*64, 512>>>();                     // inv cols + energy fused
    k_median       <<<128, 256>>>();
    k_pc           <<<32*64, 1024>>>();
    k_fsim_partial <<<4096, 256>>>(ker);
    k_final        <<<1, 512>>>(out);
}

// round 3
// speedup vs baseline: 1.2432x; 1.2432x over previous
#include <cuda_runtime.h>
#include <math.h>

// ---------------- static device scratch (no allocations allowed) ----------------
#define HW   65536      // 256*256
#define NIMG 16

__device__ float    g_yiq    [2u*NIMG*3*HW];   // [c in {x,y}][n][ch][pix] natural
__device__ float    g_fftin  [2u*NIMG*HW];     // Y*255 real
__device__ float2   g_rowspec[2u*NIMG*HW];     // after row FFT: [img][row][kcol]
__device__ float2   g_XspecT [2u*NIMG*HW];     // full spectrum TRANSPOSED: [img][kcol][krow]
__device__ float2   g_colout [512u*HW];        // after filtered col IFFT: [img*16+f][kcol][row]
__device__ float    g_filtT  [16u*HW];         // filters TRANSPOSED: [f][kcol*256+krow]
__device__ float    g_energy [2u*NIMG*4*HW];   // [cn*4+o][pix] natural
__device__ unsigned g_e2     [2u*NIMG*4*HW];   // float bits of |Eo_s0|^2
__device__ float    g_amp4   [2u*NIMG*4*HW];   // per-orientation partial amp
__device__ float    g_pc     [2u*NIMG*HW];     // natural
__device__ float    g_em     [4];
__device__ float    g_aiaj   [4];
__device__ float    g_thr    [2*NIMG*4];
__device__ float    g_part   [2*4096];

static __device__ __forceinline__ float2 cmulf(float2 a, float2 b) {
    return make_float2(a.x*b.x - a.y*b.y, a.x*b.y + a.y*b.x);
}
static __device__ __forceinline__ float2 cadd(float2 a, float2 b) {
    return make_float2(a.x + b.x, a.y + b.y);
}
static __device__ __forceinline__ float2 csub(float2 a, float2 b) {
    return make_float2(a.x - b.x, a.y - b.y);
}

// ================= warp-level 256-pt FFT (four-step: 8 regs x 32 lanes) =========
// Input : v[n2] = x[lane + 32*n2]
// Output: v[k2] = X[8*bitrev5(lane) + k2]
// SIGN = -1 forward, +1 inverse (unnormalized)

template<int SIGN>
static __device__ __forceinline__ void fft_init(float2 tw4[8], float2 twst[5], int lane)
{
    #pragma unroll
    for (int k = 0; k < 8; ++k) {
        float ang = (float)SIGN * 6.2831853071795864769f * (float)(lane * k) * (1.0f/256.0f);
        float s, c; sincosf(ang, &s, &c);
        tw4[k] = make_float2(c, s);
    }
    #pragma unroll
    for (int j = 0; j < 5; ++j) {
        int h = 16 >> j;
        float ang = (float)SIGN * 6.2831853071795864769f * (float)(lane & (h-1)) / (float)(2*h);
        float s, c; sincosf(ang, &s, &c);
        twst[j] = make_float2(c, s);
    }
}

template<int SIGN>
static __device__ __forceinline__ void warp_fft256(float2 v[8], const float2 tw4[8],
                                                   const float2 twst[5], int lane)
{
    const float R = 0.70710678118654752440f;
    const float2 W81 = make_float2( R, (float)SIGN * R);
    const float2 W82 = make_float2(0.f, (float)SIGN);
    const float2 W83 = make_float2(-R, (float)SIGN * R);
    // ---- 8-pt DIF over register slots (n2) ----
    float2 t0 = cadd(v[0], v[4]), t4 = csub(v[0], v[4]);
    float2 t1 = cadd(v[1], v[5]), t5 = cmulf(csub(v[1], v[5]), W81);
    float2 t2 = cadd(v[2], v[6]), t6 = cmulf(csub(v[2], v[6]), W82);
    float2 t3 = cadd(v[3], v[7]), t7 = cmulf(csub(v[3], v[7]), W83);
    float2 u0 = cadd(t0, t2), u2 = csub(t0, t2);
    float2 u1 = cadd(t1, t3), u3 = cmulf(csub(t1, t3), W82);
    float2 u4 = cadd(t4, t6), u6 = csub(t4, t6);
    float2 u5 = cadd(t5, t7), u7 = cmulf(csub(t5, t7), W82);
    float2 y0 = cadd(u0, u1), y1 = csub(u0, u1);
    float2 y2 = cadd(u2, u3), y3 = csub(u2, u3);
    float2 y4 = cadd(u4, u5), y5 = csub(u4, u5);
    float2 y6 = cadd(u6, u7), y7 = csub(u6, u7);
    // bit-reverse (X8[k]=y[br3(k)]) + four-step twiddle W256^{lane*k2}
    v[0] = y0;
    v[1] = cmulf(y4, tw4[1]);
    v[2] = cmulf(y2, tw4[2]);
    v[3] = cmulf(y6, tw4[3]);
    v[4] = cmulf(y1, tw4[4]);
    v[5] = cmulf(y5, tw4[5]);
    v[6] = cmulf(y3, tw4[6]);
    v[7] = cmulf(y7, tw4[7]);
    // ---- 32-pt DIF across lanes, 5 shfl stages ----
    #pragma unroll
    for (int j = 0; j < 5; ++j) {
        int h = 16 >> j;
        bool upper = (lane & h) != 0;
        float2 w = twst[j];
        #pragma unroll
        for (int k = 0; k < 8; ++k) {
            float px = __shfl_xor_sync(0xffffffffu, v[k].x, h);
            float py = __shfl_xor_sync(0xffffffffu, v[k].y, h);
            float2 r;
            if (upper) r = cmulf(make_float2(px - v[k].x, py - v[k].y), w);
            else       r = make_float2(v[k].x + px, v[k].y + py);
            v[k] = r;
        }
    }
}

static __device__ __forceinline__ int bitrev5(int l) {
    return (int)(__brev((unsigned)l) >> 27);
}

// ---------------- preprocess: 2x2 mean pool + RGB->YIQ + FFT input ----------------
__global__ void k_preprocess(const float* __restrict__ x, const float* __restrict__ y)
{
    int idx = blockIdx.x * 256 + threadIdx.x;          // 2*16*65536
    int cn  = idx >> 16;
    int pix = idx & 65535;
    int c = cn >> 4, n = cn & 15;
    int h = pix >> 8, w = pix & 255;
    const float* src = (c == 0 ? x : y) + (size_t)n * 3 * 262144;
    float rgb[3];
    #pragma unroll
    for (int ch = 0; ch < 3; ++ch) {
        const float* p = src + (size_t)ch * 262144 + (size_t)(2*h) * 512 + 2*w;
        rgb[ch] = 0.25f * (p[0] + p[1] + p[512] + p[513]);
    }
    float Y = 0.299f *rgb[0] + 0.587f *rgb[1] + 0.114f *rgb[2];
    float I = 0.5969f*rgb[0] - 0.2746f*rgb[1] - 0.3213f*rgb[2];
    float Q = 0.2115f*rgb[0] - 0.5227f*rgb[1] + 0.3112f*rgb[2];
    size_t base = (size_t)cn * 3 * HW;
    g_yiq[base + pix]         = Y;
    g_yiq[base + HW + pix]    = I;
    g_yiq[base + 2u*HW + pix] = Q;
    g_fftin[(size_t)cn * HW + pix] = Y * 255.0f;
}

// ---------------- log-Gabor filters, stored TRANSPOSED [f][kcol*256+krow] --------
__global__ void k_filters()
{
    int t = blockIdx.x * 256 + threadIdx.x;   // t = kcol*256 + krow (coalesced write)
    int krow = t & 255, kcol = t >> 8;
    float u = (float)(krow < 128 ? krow : krow - 256) * (1.0f/256.0f);
    float v = (float)(kcol < 128 ? kcol : kcol - 256) * (1.0f/256.0f);
    float r = sqrtf(u*u + v*v);
    float theta = atan2f(-v, u);
    float lp = 1.0f / (1.0f + powf(r * (1.0f/0.45f), 30.0f));
    float rs = (t == 0) ? 1.0f : r;
    float ct = cosf(theta), st = sinf(theta);
    float bo[4];
    #pragma unroll
    for (int o = 0; o < 4; ++o) {
        float thj = 0.7853981633974483f * (float)o;
        float cj = cosf(thj), sj = sinf(thj);
        float ds = st*cj - ct*sj;
        float dc = ct*cj + st*sj;
        float dt = atan2f(ds, dc);
        bo[o] = expf(-dt*dt / 0.85674050f);          // 2*sigma_theta^2
    }
    #pragma unroll
    for (int s = 0; s < 4; ++s) {
        float f0 = 1.0f / (6.0f * (float)(1 << s));
        float lr = logf(rs / f0);
        float a = expf(-lr*lr / 0.52941847f) * lp;   // 2*ln(sigma_f)^2
        if (t == 0) a = 0.0f;
        #pragma unroll
        for (int o = 0; o < 4; ++o)
            g_filtT[(size_t)(s*4 + o) * HW + t] = a * bo[o];
    }
}

// em[o] = sum filt[s=0,o]^2 ; sum_aiaj[o] = sum_k ((F(k)+F(-k))/2)^2
// (index-negation formula acts per byte, valid in transposed layout too)
__global__ void k_filter_stats()
{
    int o = blockIdx.x;
    int tid = threadIdx.x;
    float em_acc = 0.0f, aj_acc = 0.0f;
    for (int pix = tid; pix < HW; pix += 256) {
        int i = pix >> 8, j = pix & 255;
        int npix = (((256 - i) & 255) << 8) | ((256 - j) & 255);
        float f0 = g_filtT[(size_t)o * HW + pix];
        em_acc += f0 * f0;
        float F  = f0
                 + g_filtT[(size_t)(4  + o) * HW + pix]
                 + g_filtT[(size_t)(8  + o) * HW + pix]
                 + g_filtT[(size_t)(12 + o) * HW + pix];
        float Fn = g_filtT[(size_t)(o)      * HW + npix]
                 + g_filtT[(size_t)(4  + o) * HW + npix]
                 + g_filtT[(size_t)(8  + o) * HW + npix]
                 + g_filtT[(size_t)(12 + o) * HW + npix];
        float hh = 0.5f * (F + Fn);
        aj_acc += hh * hh;
    }
    __shared__ float se[256], sa[256];
    se[tid] = em_acc; sa[tid] = aj_acc;
    __syncthreads();
    for (int s = 128; s > 0; s >>= 1) {
        if (tid < s) { se[tid] += se[tid + s]; sa[tid] += sa[tid + s]; }
        __syncthreads();
    }
    if (tid == 0) { g_em[o] = se[0]; g_aiaj[o] = sa[0]; }
}

// ---------------- Pass A: forward row FFT (real input), natural store -------------
__global__ void __launch_bounds__(512) k_fft_rows_fwd()
{
    int lane = threadIdx.x & 31, wid = threadIdx.x >> 5;
    int line = blockIdx.x * 16 + wid;                  // img*256 + row, 0..8191
    float2 tw4[8], twst[5];
    fft_init<-1>(tw4, twst, lane);
    const float* in = g_fftin + (size_t)line * 256;
    float2 v[8];
    #pragma unroll
    for (int n = 0; n < 8; ++n) v[n] = make_float2(in[lane + 32*n], 0.0f);
    warp_fft256<-1>(v, tw4, twst, lane);
    int br = bitrev5(lane);
    float4* out = (float4*)(g_rowspec + (size_t)line * 256 + 8*br);
    out[0] = make_float4(v[0].x, v[0].y, v[1].x, v[1].y);
    out[1] = make_float4(v[2].x, v[2].y, v[3].x, v[3].y);
    out[2] = make_float4(v[4].x, v[4].y, v[5].x, v[5].y);
    out[3] = make_float4(v[6].x, v[6].y, v[7].x, v[7].y);
}

// ---------------- Pass B: forward column FFT, store transposed [kcol][krow] -------
__global__ void __launch_bounds__(512) k_fft_cols_fwd()
{
    __shared__ float2 sm[256][17];
    int tid = threadIdx.x, lane = tid & 31, wid = tid >> 5;
    int img = blockIdx.x >> 4;
    int c0  = (blockIdx.x & 15) << 4;
    const float2* src = g_rowspec + (size_t)img * HW;
    for (int i = tid; i < 4096; i += 512) {
        int row = i >> 4, col = i & 15;
        sm[row][col] = src[(size_t)row * 256 + c0 + col];
    }
    __syncthreads();
    float2 tw4[8], twst[5];
    fft_init<-1>(tw4, twst, lane);
    float2 v[8];
    #pragma unroll
    for (int n = 0; n < 8; ++n) v[n] = sm[lane + 32*n][wid];
    warp_fft256<-1>(v, tw4, twst, lane);
    int br = bitrev5(lane);
    float4* out = (float4*)(g_XspecT + (size_t)img * HW + (size_t)(c0 + wid) * 256 + 8*br);
    out[0] = make_float4(v[0].x, v[0].y, v[1].x, v[1].y);
    out[1] = make_float4(v[2].x, v[2].y, v[3].x, v[3].y);
    out[2] = make_float4(v[4].x, v[4].y, v[5].x, v[5].y);
    out[3] = make_float4(v[6].x, v[6].y, v[7].x, v[7].y);
}

// ---------------- Pass C: filtered inverse column FFT, 16 filters per column ------
// Reads X column ONCE into regs; no shared memory, no syncs.
__global__ void __launch_bounds__(512) k_ifft_cols_filt()
{
    int lane = threadIdx.x & 31, wid = threadIdx.x >> 5;
    int img = blockIdx.x >> 4;
    int col = ((blockIdx.x & 15) << 4) + wid;          // kcol
    float2 tw4[8], twst[5];
    fft_init<1>(tw4, twst, lane);
    const float2* xcol = g_XspecT + (size_t)img * HW + (size_t)col * 256;
    float2 xc[8];
    #pragma unroll
    for (int n = 0; n < 8; ++n) xc[n] = xcol[lane + 32*n];
    int br = bitrev5(lane);
    #pragma unroll 1
    for (int f = 0; f < 16; ++f) {
        const float* fcol = g_filtT + (size_t)f * HW + (size_t)col * 256;
        float2 v[8];
        #pragma unroll
        for (int n = 0; n < 8; ++n) {
            float g = fcol[lane + 32*n] * (1.0f/256.0f);
            v[n] = make_float2(xc[n].x * g, xc[n].y * g);
        }
        warp_fft256<1>(v, tw4, twst, lane);
        float4* out = (float4*)(g_colout + ((size_t)(img*16 + f)) * HW
                                          + (size_t)col * 256 + 8*br);
        out[0] = make_float4(v[0].x, v[0].y, v[1].x, v[1].y);
        out[1] = make_float4(v[2].x, v[2].y, v[3].x, v[3].y);
        out[2] = make_float4(v[4].x, v[4].y, v[5].x, v[5].y);
        out[3] = make_float4(v[6].x, v[6].y, v[7].x, v[7].y);
    }
}

// ---------------- Pass D: inverse row FFT (4 scales) + energy, fused --------------
// block = 256 thr (8 warps = 8 rows); grid = cn(32) * o(4) * rgroup(32)
__global__ void __launch_bounds__(256) k_ifft_rows_energy()
{
    __shared__ float2 sm[256][9];
    int tid = threadIdx.x, lane = tid & 31, wid = tid >> 5;   // wid 0..7
    int b  = blockIdx.x;
    int rg = b & 31;
    int o  = (b >> 5) & 3;
    int cn = b >> 7;
    int r0 = rg << 3;
    float2 tw4[8], twst[5];
    fft_init<1>(tw4, twst, lane);
    int br = bitrev5(lane);

    float er[4][8], ei[4][8];
    #pragma unroll
    for (int s = 0; s < 4; ++s) {
        const float2* src = g_colout + ((size_t)(cn*16 + s*4 + o)) * HW;
        __syncthreads();
        for (int i = tid; i < 2048; i += 256) {
            int c = i >> 3, rr = i & 7;
            sm[c][rr] = src[(size_t)c * 256 + r0 + rr];
        }
        __syncthreads();
        float2 v[8];
        #pragma unroll
        for (int n = 0; n < 8; ++n) v[n] = sm[lane + 32*n][wid];
        warp_fft256<1>(v, tw4, twst, lane);
        #pragma unroll
        for (int k = 0; k < 8; ++k) {
            er[s][k] = v[k].x * (1.0f/256.0f);
            ei[s][k] = v[k].y * (1.0f/256.0f);
        }
    }

    int row = r0 + wid;
    float env[8], ampv[8]; unsigned e2v[8];
    #pragma unroll
    for (int k = 0; k < 8; ++k) {
        float sx = er[0][k] + er[1][k] + er[2][k] + er[3][k];
        float sy = ei[0][k] + ei[1][k] + ei[2][k] + ei[3][k];
        float invm = 1.0f / (sqrtf(sx*sx + sy*sy) + 1e-8f);
        float mr = sx * invm, mi = sy * invm;
        float en = 0.0f, am = 0.0f;
        #pragma unroll
        for (int s = 0; s < 4; ++s) {
            en += (er[s][k]*mr + ei[s][k]*mi) - fabsf(ei[s][k]*mr - er[s][k]*mi);
            am += sqrtf(er[s][k]*er[s][k] + ei[s][k]*ei[s][k]);
        }
        env[k] = en; ampv[k] = am;
        e2v[k] = __float_as_uint(er[0][k]*er[0][k] + ei[0][k]*ei[0][k]);
    }
    size_t base = ((size_t)(cn*4 + o)) * HW + (size_t)row * 256 + 8*br;
    float4* ep = (float4*)(g_energy + base);
    ep[0] = make_float4(env[0], env[1], env[2], env[3]);
    ep[1] = make_float4(env[4], env[5], env[6], env[7]);
    float4* ap = (float4*)(g_amp4 + base);
    ap[0] = make_float4(ampv[0], ampv[1], ampv[2], ampv[3]);
    ap[1] = make_float4(ampv[4], ampv[5], ampv[6], ampv[7]);
    uint4* qp = (uint4*)(g_e2 + base);
    qp[0] = make_uint4(e2v[0], e2v[1], e2v[2], e2v[3]);
    qp[1] = make_uint4(e2v[4], e2v[5], e2v[6], e2v[7]);
}

// ---------------- exact median via byte-radix select (warp-aggregated) ------------
__global__ void k_median()
{
    const unsigned* data = g_e2 + (size_t)blockIdx.x * HW;  // blockIdx = cn*4+o
    __shared__ unsigned hist[256];
    __shared__ unsigned s_prefix;
    __shared__ int s_rank;
    int tid  = threadIdx.x;
    int lane = tid & 31;
    if (tid == 0) { s_prefix = 0u; s_rank = 32767; }        // (HW-1)//2
    __syncthreads();
    for (int shift = 24; shift >= 0; shift -= 8) {
        hist[tid] = 0u;
        __syncthreads();
        unsigned prefix = s_prefix;
        unsigned himask = (shift == 24) ? 0u : (0xFFFFFFFFu << (shift + 8));
        for (int i = tid; i < HW; i += 256) {
            unsigned v = data[i];
            bool pred = ((v & himask) == prefix);
            unsigned bk = pred ? ((v >> shift) & 255u) : 256u;
            unsigned m  = __match_any_sync(0xffffffffu, bk);
            if (pred && (unsigned)(__ffs(m) - 1) == (unsigned)lane)
                atomicAdd(&hist[bk], (unsigned)__popc(m));
        }
        __syncthreads();
        if (tid == 0) {
            int r = s_rank; unsigned cum = 0; int bk = 0;
            for (; bk < 256; ++bk) {
                if (cum + hist[bk] > (unsigned)r) break;
                cum += hist[bk];
            }
            s_prefix = prefix | ((unsigned)bk << shift);
            s_rank   = r - (int)cum;
        }
        __syncthreads();
    }
    if (tid == 0) {
        int o = blockIdx.x & 3;
        float median  = __uint_as_float(s_prefix);
        float mean_e2 = median * 1.4426950408889634f;       // -median/ln(0.5)
        float tau = sqrtf(mean_e2 / g_em[o] * g_aiaj[o]);
        g_thr[blockIdx.x] = tau * 1.5079922765f;            // (c + 2d)/1.7
    }
}

// ---------------- pc map (all natural layout now) ----------------
__global__ void k_pc()
{
    unsigned idx = blockIdx.x * 256 + threadIdx.x;          // 32*HW
    size_t cn  = idx >> 16;
    size_t pix = idx & 65535;
    float a = 0.0f, acc = 0.0f;
    #pragma unroll
    for (int o = 0; o < 4; ++o) {
        size_t off = (cn*4 + o) * HW + pix;
        a   += g_amp4[off];
        acc += fmaxf(g_energy[off] - g_thr[cn*4 + o], 0.0f);
    }
    g_pc[idx] = acc / (a + 1e-8f);
}

// ---------------- FSIM pointwise + per-block reduction ----------------
__global__ void k_fsim_partial(const float* __restrict__ ker)
{
    const float T1 = 0.85f;
    const float T2 = 160.0f / 65025.0f;
    const float T3 = 200.0f / 65025.0f;
    const float T4 = 200.0f / 65025.0f;
    int tid = threadIdx.x;
    int n   = blockIdx.x >> 8;
    int pix = ((blockIdx.x & 255) << 8) | tid;
    int h = pix >> 8, w = pix & 255;

    const float* Yx = g_yiq + ((size_t)(0*NIMG + n) * 3 + 0) * HW;
    const float* Yy = g_yiq + ((size_t)(1*NIMG + n) * 3 + 0) * HW;

    float g0x = 0.f, g1x = 0.f, g0y = 0.f, g1y = 0.f;
    #pragma unroll
    for (int ky = 0; ky < 3; ++ky) {
        int hh = h + ky - 1;
        if (hh < 0 || hh > 255) continue;
        #pragma unroll
        for (int kx = 0; kx < 3; ++kx) {
            int ww = w + kx - 1;
            if (ww < 0 || ww > 255) continue;
            float vx = Yx[hh*256 + ww], vy = Yy[hh*256 + ww];
            float k0 = ker[ky*3 + kx], k1 = ker[9 + ky*3 + kx];
            g0x += k0*vx; g1x += k1*vx;
            g0y += k0*vy; g1y += k1*vy;
        }
    }
    float gX = sqrtf(g0x*g0x + g1x*g1x);
    float gY = sqrtf(g0y*g0y + g1y*g1y);

    float pcx = g_pc[(size_t)(0*NIMG + n) * HW + pix];
    float pcy = g_pc[(size_t)(1*NIMG + n) * HW + pix];
    float s_pc = (2.0f*pcx*pcy + T1) / (pcx*pcx + pcy*pcy + T1);
    float s_g  = (2.0f*gX*gY + T2) / (gX*gX + gY*gY + T2);

    float ix = g_yiq[((size_t)(0*NIMG + n) * 3 + 1) * HW + pix];
    float iy = g_yiq[((size_t)(1*NIMG + n) * 3 + 1) * HW + pix];
    float qx = g_yiq[((size_t)(0*NIMG + n) * 3 + 2) * HW + pix];
    float qy = g_yiq[((size_t)(1*NIMG + n) * 3 + 2) * HW + pix];
    float s_i = (2.0f*ix*iy + T3) / (ix*ix + iy*iy + T3);
    float s_q = (2.0f*qx*qy + T4) / (qx*qx + qy*qy + T4);
    float siq = s_i * s_q;
    float slam = powf(fabsf(siq), 0.03f) * (siq < 0.0f ? 0.99556196f : 1.0f); // cos(0.03*pi)

    float pcm = fmaxf(pcx, pcy);
    float num = s_pc * s_g * slam * pcm;
    float den = pcm;

    __shared__ float sn[256], sd[256];
    sn[tid] = num; sd[tid] = den;
    __syncthreads();
    for (int s = 128; s > 0; s >>= 1) {
        if (tid < s) { sn[tid] += sn[tid + s]; sd[tid] += sd[tid + s]; }
        __syncthreads();
    }
    if (tid == 0) {
        g_part[blockIdx.x]        = sn[0];
        g_part[4096 + blockIdx.x] = sd[0];
    }
}

__global__ void k_final(float* __restrict__ out)
{
    int tid = threadIdx.x;          // 512
    int n = tid >> 5, lane = tid & 31;
    float num = 0.f, den = 0.f;
    for (int i = lane; i < 256; i += 32) {
        num += g_part[n*256 + i];
        den += g_part[4096 + n*256 + i];
    }
    #pragma unroll
    for (int off = 16; off > 0; off >>= 1) {
        num += __shfl_down_sync(0xffffffffu, num, off);
        den += __shfl_down_sync(0xffffffffu, den, off);
    }
    __shared__ float fs[16];
    if (lane == 0) fs[n] = num / den;
    __syncthreads();
    if (tid == 0) {
        float s = 0.f;
        #pragma unroll
        for (int k = 0; k < 16; ++k) s += fs[k];
        out[0] = s * (1.0f / 16.0f);
    }
}

// ---------------- launch ----------------
extern "C" void kernel_launch(void* const* d_in, const int* in_sizes, int n_in,
                              void* d_out, int out_size)
{
    (void)in_sizes; (void)n_in; (void)out_size;
    const float* x   = (const float*)d_in[0];
    const float* y   = (const float*)d_in[1];
    const float* ker = (const float*)d_in[2];
    float* out = (float*)d_out;

    k_preprocess       <<<8192, 256>>>(x, y);
    k_filters          <<<256, 256>>>();
    k_filter_stats     <<<4, 256>>>();
    k_fft_rows_fwd     <<<512, 512>>>();
    k_fft_cols_fwd     <<<512, 512>>>();
    k_ifft_cols_filt   <<<512, 512>>>();
    k_ifft_rows_energy <<<4096, 256>>>();
    k_median           <<<128, 256>>>();
    k_pc               <<<8192, 256>>>();
    k_fsim_partial     <<<4096, 256>>>(ker);
    k_final            <<<1, 512>>>(out);
}

// round 4
// speedup vs baseline: 1.3254x; 1.0661x over previous
#include <cuda_runtime.h>
#include <math.h>

// ---------------- static device scratch (no allocations allowed) ----------------
#define HW   65536      // 256*256
#define NIMG 16

__device__ float    g_yiq    [2u*NIMG*3*HW];   // [c in {x,y}][n][ch][pix] natural
__device__ float    g_fftin  [2u*NIMG*HW];     // Y*255 real
__device__ float2   g_rowspec[2u*NIMG*HW];     // after row FFT: [img][row][kcol]
__device__ float2   g_XspecT [2u*NIMG*HW];     // full spectrum TRANSPOSED: [img][kcol][krow]
__device__ float2   g_colout [512u*HW];        // after filtered col IFFT: [img*16+f][kcol][row]
__device__ float    g_filtT  [16u*HW];         // filters TRANSPOSED: [f][kcol*256+krow]
__device__ float    g_energy [2u*NIMG*4*HW];   // [cn*4+o][pix] natural
__device__ unsigned g_e2     [2u*NIMG*4*HW];   // float bits of |Eo_s0|^2
__device__ float    g_amp4   [2u*NIMG*4*HW];   // per-orientation partial amp
__device__ float    g_pc     [2u*NIMG*HW];     // natural
__device__ float    g_em     [4];
__device__ float    g_aiaj   [4];
__device__ float    g_thr    [2*NIMG*4];
__device__ float    g_part   [2*4096];
// twiddle tables: [0..255] = tw4 [k][lane], [256..415] = twst [j][lane]
__device__ float2   g_twf    [416];            // forward (sign -1)
__device__ float2   g_twi    [416];            // inverse (sign +1)

static __device__ __forceinline__ float2 cmulf(float2 a, float2 b) {
    return make_float2(a.x*b.x - a.y*b.y, a.x*b.y + a.y*b.x);
}
static __device__ __forceinline__ float2 cadd(float2 a, float2 b) {
    return make_float2(a.x + b.x, a.y + b.y);
}
static __device__ __forceinline__ float2 csub(float2 a, float2 b) {
    return make_float2(a.x - b.x, a.y - b.y);
}
static __device__ __forceinline__ int bitrev5(int l) {
    return (int)(__brev((unsigned)l) >> 27);
}

// ---------------- twiddle tables (computed once, bitwise same as old sincosf) ----
__global__ void k_twiddles()
{
    int lane = threadIdx.x;      // 32 threads
    #pragma unroll
    for (int sgn = 0; sgn < 2; ++sgn) {
        float sign = sgn ? 1.0f : -1.0f;
        float2* tbl = sgn ? g_twi : g_twf;
        for (int k = 0; k < 8; ++k) {
            float ang = sign * 6.2831853071795864769f * (float)(lane * k) * (1.0f/256.0f);
            float s, c; sincosf(ang, &s, &c);
            tbl[k*32 + lane] = make_float2(c, s);
        }
        for (int j = 0; j < 5; ++j) {
            int h = 16 >> j;
            float ang = sign * 6.2831853071795864769f * (float)(lane & (h-1)) / (float)(2*h);
            float s, c; sincosf(ang, &s, &c);
            tbl[256 + j*32 + lane] = make_float2(c, s);
        }
    }
}

// ================= warp-level 256-pt FFT (twiddles from shared memory) ==========
// Input : v[n2] = x[lane + 32*n2];  Output: v[k2] = X[8*bitrev5(lane) + k2]
// tw4 = s_tw, twst = s_tw + 256 (indexed [k*32+lane] / [j*32+lane])
template<int SIGN>
static __device__ __forceinline__ void warp_fft256_s(float2 v[8], const float2* __restrict__ s_tw,
                                                     int lane)
{
    const float R = 0.70710678118654752440f;
    const float2 W81 = make_float2( R, (float)SIGN * R);
    const float2 W82 = make_float2(0.f, (float)SIGN);
    const float2 W83 = make_float2(-R, (float)SIGN * R);
    // ---- 8-pt DIF over register slots (n2) ----
    float2 t0 = cadd(v[0], v[4]), t4 = csub(v[0], v[4]);
    float2 t1 = cadd(v[1], v[5]), t5 = cmulf(csub(v[1], v[5]), W81);
    float2 t2 = cadd(v[2], v[6]), t6 = cmulf(csub(v[2], v[6]), W82);
    float2 t3 = cadd(v[3], v[7]), t7 = cmulf(csub(v[3], v[7]), W83);
    float2 u0 = cadd(t0, t2), u2 = csub(t0, t2);
    float2 u1 = cadd(t1, t3), u3 = cmulf(csub(t1, t3), W82);
    float2 u4 = cadd(t4, t6), u6 = csub(t4, t6);
    float2 u5 = cadd(t5, t7), u7 = cmulf(csub(t5, t7), W82);
    float2 y0 = cadd(u0, u1), y1 = csub(u0, u1);
    float2 y2 = cadd(u2, u3), y3 = csub(u2, u3);
    float2 y4 = cadd(u4, u5), y5 = csub(u4, u5);
    float2 y6 = cadd(u6, u7), y7 = csub(u6, u7);
    // bit-reverse (X8[k]=y[br3(k)]) + four-step twiddle W256^{lane*k2}
    v[0] = y0;
    v[1] = cmulf(y4, s_tw[1*32 + lane]);
    v[2] = cmulf(y2, s_tw[2*32 + lane]);
    v[3] = cmulf(y6, s_tw[3*32 + lane]);
    v[4] = cmulf(y1, s_tw[4*32 + lane]);
    v[5] = cmulf(y5, s_tw[5*32 + lane]);
    v[6] = cmulf(y3, s_tw[6*32 + lane]);
    v[7] = cmulf(y7, s_tw[7*32 + lane]);
    // ---- 32-pt DIF across lanes, 5 shfl stages ----
    #pragma unroll
    for (int j = 0; j < 5; ++j) {
        int h = 16 >> j;
        bool upper = (lane & h) != 0;
        float2 w = s_tw[256 + j*32 + lane];
        #pragma unroll
        for (int k = 0; k < 8; ++k) {
            float px = __shfl_xor_sync(0xffffffffu, v[k].x, h);
            float py = __shfl_xor_sync(0xffffffffu, v[k].y, h);
            float2 r;
            if (upper) r = cmulf(make_float2(px - v[k].x, py - v[k].y), w);
            else       r = make_float2(v[k].x + px, v[k].y + py);
            v[k] = r;
        }
    }
}

// ---------------- preprocess: 2x2 mean pool + RGB->YIQ (2 pixels/thread) ----------
__global__ void k_preprocess(const float* __restrict__ x, const float* __restrict__ y)
{
    int idx = blockIdx.x * 256 + threadIdx.x;   // 2*16*HW/2 = 1M threads
    int cn  = idx >> 15;
    int rem = idx & 32767;
    int pix0 = rem * 2;
    int h = pix0 >> 8, w = pix0 & 255;          // w even
    int c = cn >> 4, n = cn & 15;
    const float* src = (c == 0 ? x : y) + (size_t)n * 3 * 262144;
    float rgb0[3], rgb1[3];
    #pragma unroll
    for (int ch = 0; ch < 3; ++ch) {
        const float4* pa = (const float4*)(src + (size_t)ch * 262144 + (size_t)(2*h) * 512 + 2*w);
        const float4* pb = (const float4*)(src + (size_t)ch * 262144 + (size_t)(2*h+1) * 512 + 2*w);
        float4 a = pa[0], b = pb[0];
        rgb0[ch] = 0.25f * (a.x + a.y + b.x + b.y);
        rgb1[ch] = 0.25f * (a.z + a.w + b.z + b.w);
    }
    float Y0 = 0.299f *rgb0[0] + 0.587f *rgb0[1] + 0.114f *rgb0[2];
    float I0 = 0.5969f*rgb0[0] - 0.2746f*rgb0[1] - 0.3213f*rgb0[2];
    float Q0 = 0.2115f*rgb0[0] - 0.5227f*rgb0[1] + 0.3112f*rgb0[2];
    float Y1 = 0.299f *rgb1[0] + 0.587f *rgb1[1] + 0.114f *rgb1[2];
    float I1 = 0.5969f*rgb1[0] - 0.2746f*rgb1[1] - 0.3213f*rgb1[2];
    float Q1 = 0.2115f*rgb1[0] - 0.5227f*rgb1[1] + 0.3112f*rgb1[2];
    size_t base = (size_t)cn * 3 * HW;
    *(float2*)(g_yiq + base + pix0)         = make_float2(Y0, Y1);
    *(float2*)(g_yiq + base + HW + pix0)    = make_float2(I0, I1);
    *(float2*)(g_yiq + base + 2u*HW + pix0) = make_float2(Q0, Q1);
    *(float2*)(g_fftin + (size_t)cn * HW + pix0) = make_float2(Y0 * 255.0f, Y1 * 255.0f);
}

// ---------------- log-Gabor filters, stored TRANSPOSED [f][kcol*256+krow] --------
__global__ void k_filters()
{
    int t = blockIdx.x * 256 + threadIdx.x;   // t = kcol*256 + krow
    int krow = t & 255, kcol = t >> 8;
    float u = (float)(krow < 128 ? krow : krow - 256) * (1.0f/256.0f);
    float v = (float)(kcol < 128 ? kcol : kcol - 256) * (1.0f/256.0f);
    float r = sqrtf(u*u + v*v);
    float theta = atan2f(-v, u);
    float lp = 1.0f / (1.0f + powf(r * (1.0f/0.45f), 30.0f));
    float rs = (t == 0) ? 1.0f : r;
    float ct = cosf(theta), st = sinf(theta);
    float bo[4];
    #pragma unroll
    for (int o = 0; o < 4; ++o) {
        float thj = 0.7853981633974483f * (float)o;
        float cj = cosf(thj), sj = sinf(thj);
        float ds = st*cj - ct*sj;
        float dc = ct*cj + st*sj;
        float dt = atan2f(ds, dc);
        bo[o] = expf(-dt*dt / 0.85674050f);          // 2*sigma_theta^2
    }
    #pragma unroll
    for (int s = 0; s < 4; ++s) {
        float f0 = 1.0f / (6.0f * (float)(1 << s));
        float lr = logf(rs / f0);
        float a = expf(-lr*lr / 0.52941847f) * lp;   // 2*ln(sigma_f)^2
        if (t == 0) a = 0.0f;
        #pragma unroll
        for (int o = 0; o < 4; ++o)
            g_filtT[(size_t)(s*4 + o) * HW + t] = a * bo[o];
    }
}

// em[o] = sum filt[s=0,o]^2 ; sum_aiaj[o] = sum_k ((F(k)+F(-k))/2)^2
__global__ void k_filter_stats()
{
    int o = blockIdx.x;
    int tid = threadIdx.x;
    float em_acc = 0.0f, aj_acc = 0.0f;
    for (int pix = tid; pix < HW; pix += 256) {
        int i = pix >> 8, j = pix & 255;
        int npix = (((256 - i) & 255) << 8) | ((256 - j) & 255);
        float f0 = g_filtT[(size_t)o * HW + pix];
        em_acc += f0 * f0;
        float F  = f0
                 + g_filtT[(size_t)(4  + o) * HW + pix]
                 + g_filtT[(size_t)(8  + o) * HW + pix]
                 + g_filtT[(size_t)(12 + o) * HW + pix];
        float Fn = g_filtT[(size_t)(o)      * HW + npix]
                 + g_filtT[(size_t)(4  + o) * HW + npix]
                 + g_filtT[(size_t)(8  + o) * HW + npix]
                 + g_filtT[(size_t)(12 + o) * HW + npix];
        float hh = 0.5f * (F + Fn);
        aj_acc += hh * hh;
    }
    __shared__ float se[256], sa[256];
    se[tid] = em_acc; sa[tid] = aj_acc;
    __syncthreads();
    for (int s = 128; s > 0; s >>= 1) {
        if (tid < s) { se[tid] += se[tid + s]; sa[tid] += sa[tid + s]; }
        __syncthreads();
    }
    if (tid == 0) { g_em[o] = se[0]; g_aiaj[o] = sa[0]; }
}

// ---------------- Pass A: forward row FFT (real input), natural store -------------
__global__ void __launch_bounds__(256) k_fft_rows_fwd()
{
    __shared__ float2 s_tw[416];
    int tid = threadIdx.x, lane = tid & 31, wid = tid >> 5;
    for (int i = tid; i < 416; i += 256) s_tw[i] = g_twf[i];
    __syncthreads();
    int line = blockIdx.x * 8 + wid;                  // img*256 + row
    const float* in = g_fftin + (size_t)line * 256;
    float2 v[8];
    #pragma unroll
    for (int n = 0; n < 8; ++n) v[n] = make_float2(in[lane + 32*n], 0.0f);
    warp_fft256_s<-1>(v, s_tw, lane);
    int br = bitrev5(lane);
    float4* out = (float4*)(g_rowspec + (size_t)line * 256 + 8*br);
    out[0] = make_float4(v[0].x, v[0].y, v[1].x, v[1].y);
    out[1] = make_float4(v[2].x, v[2].y, v[3].x, v[3].y);
    out[2] = make_float4(v[4].x, v[4].y, v[5].x, v[5].y);
    out[3] = make_float4(v[6].x, v[6].y, v[7].x, v[7].y);
}

// ---------------- Pass B: forward column FFT, store transposed [kcol][krow] -------
__global__ void __launch_bounds__(256) k_fft_cols_fwd()
{
    __shared__ float2 sm[256][9];
    __shared__ float2 s_tw[416];
    int tid = threadIdx.x, lane = tid & 31, wid = tid >> 5;
    for (int i = tid; i < 416; i += 256) s_tw[i] = g_twf[i];
    int img = blockIdx.x >> 5;
    int c0  = (blockIdx.x & 31) << 3;
    const float2* src = g_rowspec + (size_t)img * HW;
    for (int i = tid; i < 2048; i += 256) {
        int row = i >> 3, col = i & 7;
        sm[row][col] = src[(size_t)row * 256 + c0 + col];
    }
    __syncthreads();
    float2 v[8];
    #pragma unroll
    for (int n = 0; n < 8; ++n) v[n] = sm[lane + 32*n][wid];
    warp_fft256_s<-1>(v, s_tw, lane);
    int br = bitrev5(lane);
    float4* out = (float4*)(g_XspecT + (size_t)img * HW + (size_t)(c0 + wid) * 256 + 8*br);
    out[0] = make_float4(v[0].x, v[0].y, v[1].x, v[1].y);
    out[1] = make_float4(v[2].x, v[2].y, v[3].x, v[3].y);
    out[2] = make_float4(v[4].x, v[4].y, v[5].x, v[5].y);
    out[3] = make_float4(v[6].x, v[6].y, v[7].x, v[7].y);
}

// ---------------- Pass C: filtered inverse column FFT, 16 filters per warp --------
// 128-thread blocks for occupancy; X column loaded once into regs.
__global__ void __launch_bounds__(128) k_ifft_cols_filt()
{
    __shared__ float2 s_tw[416];
    int tid = threadIdx.x, lane = tid & 31, wid = tid >> 5;
    for (int i = tid; i < 416; i += 128) s_tw[i] = g_twi[i];
    __syncthreads();
    int img = blockIdx.x >> 6;
    int col = ((blockIdx.x & 63) << 2) + wid;          // kcol
    const float2* xcol = g_XspecT + (size_t)img * HW + (size_t)col * 256;
    float2 xc[8];
    #pragma unroll
    for (int n = 0; n < 8; ++n) xc[n] = xcol[lane + 32*n];
    int br = bitrev5(lane);
    #pragma unroll 1
    for (int f = 0; f < 16; ++f) {
        const float* fcol = g_filtT + (size_t)f * HW + (size_t)col * 256;
        float2 v[8];
        #pragma unroll
        for (int n = 0; n < 8; ++n) {
            float g = fcol[lane + 32*n] * (1.0f/256.0f);
            v[n] = make_float2(xc[n].x * g, xc[n].y * g);
        }
        warp_fft256_s<1>(v, s_tw, lane);
        float4* out = (float4*)(g_colout + ((size_t)(img*16 + f)) * HW
                                          + (size_t)col * 256 + 8*br);
        out[0] = make_float4(v[0].x, v[0].y, v[1].x, v[1].y);
        out[1] = make_float4(v[2].x, v[2].y, v[3].x, v[3].y);
        out[2] = make_float4(v[4].x, v[4].y, v[5].x, v[5].y);
        out[3] = make_float4(v[6].x, v[6].y, v[7].x, v[7].y);
    }
}

// ---------------- Pass D: inverse row FFT (4 scales) + energy, fused --------------
// 128 thr (4 warps = 4 rows); grid = cn(32) * o(4) * rgroup(64)
__global__ void __launch_bounds__(128) k_ifft_rows_energy()
{
    __shared__ float2 sm[256][5];
    __shared__ float2 s_tw[416];
    int tid = threadIdx.x, lane = tid & 31, wid = tid >> 5;   // wid 0..3
    for (int i = tid; i < 416; i += 128) s_tw[i] = g_twi[i];
    int b  = blockIdx.x;
    int rg = b & 63;
    int o  = (b >> 6) & 3;
    int cn = b >> 8;
    int r0 = rg << 2;
    int br = bitrev5(lane);

    float er[4][8], ei[4][8];
    #pragma unroll
    for (int s = 0; s < 4; ++s) {
        const float2* src = g_colout + ((size_t)(cn*16 + s*4 + o)) * HW;
        __syncthreads();
        for (int i = tid; i < 1024; i += 128) {
            int c = i >> 2, rr = i & 3;
            sm[c][rr] = src[(size_t)c * 256 + r0 + rr];
        }
        __syncthreads();
        float2 v[8];
        #pragma unroll
        for (int n = 0; n < 8; ++n) v[n] = sm[lane + 32*n][wid];
        warp_fft256_s<1>(v, s_tw, lane);
        #pragma unroll
        for (int k = 0; k < 8; ++k) {
            er[s][k] = v[k].x * (1.0f/256.0f);
            ei[s][k] = v[k].y * (1.0f/256.0f);
        }
    }

    int row = r0 + wid;
    float env[8], ampv[8]; unsigned e2v[8];
    #pragma unroll
    for (int k = 0; k < 8; ++k) {
        float sx = er[0][k] + er[1][k] + er[2][k] + er[3][k];
        float sy = ei[0][k] + ei[1][k] + ei[2][k] + ei[3][k];
        float invm = 1.0f / (sqrtf(sx*sx + sy*sy) + 1e-8f);
        float mr = sx * invm, mi = sy * invm;
        float en = 0.0f, am = 0.0f;
        #pragma unroll
        for (int s = 0; s < 4; ++s) {
            en += (er[s][k]*mr + ei[s][k]*mi) - fabsf(ei[s][k]*mr - er[s][k]*mi);
            am += sqrtf(er[s][k]*er[s][k] + ei[s][k]*ei[s][k]);
        }
        env[k] = en; ampv[k] = am;
        e2v[k] = __float_as_uint(er[0][k]*er[0][k] + ei[0][k]*ei[0][k]);
    }
    size_t base = ((size_t)(cn*4 + o)) * HW + (size_t)row * 256 + 8*br;
    float4* ep = (float4*)(g_energy + base);
    ep[0] = make_float4(env[0], env[1], env[2], env[3]);
    ep[1] = make_float4(env[4], env[5], env[6], env[7]);
    float4* ap = (float4*)(g_amp4 + base);
    ap[0] = make_float4(ampv[0], ampv[1], ampv[2], ampv[3]);
    ap[1] = make_float4(ampv[4], ampv[5], ampv[6], ampv[7]);
    uint4* qp = (uint4*)(g_e2 + base);
    qp[0] = make_uint4(e2v[0], e2v[1], e2v[2], e2v[3]);
    qp[1] = make_uint4(e2v[4], e2v[5], e2v[6], e2v[7]);
}

// ---------------- exact median via byte-radix select (warp-aggregated) ------------
__global__ void k_median()
{
    const unsigned* data = g_e2 + (size_t)blockIdx.x * HW;  // blockIdx = cn*4+o
    __shared__ unsigned hist[256];
    __shared__ unsigned s_prefix;
    __shared__ int s_rank;
    int tid  = threadIdx.x;
    int lane = tid & 31;
    if (tid == 0) { s_prefix = 0u; s_rank = 32767; }        // (HW-1)//2
    __syncthreads();
    for (int shift = 24; shift >= 0; shift -= 8) {
        hist[tid] = 0u;
        __syncthreads();
        unsigned prefix = s_prefix;
        unsigned himask = (shift == 24) ? 0u : (0xFFFFFFFFu << (shift + 8));
        for (int i = tid; i < HW; i += 256) {
            unsigned v = data[i];
            bool pred = ((v & himask) == prefix);
            unsigned bk = pred ? ((v >> shift) & 255u) : 256u;
            unsigned m  = __match_any_sync(0xffffffffu, bk);
            if (pred && (unsigned)(__ffs(m) - 1) == (unsigned)lane)
                atomicAdd(&hist[bk], (unsigned)__popc(m));
        }
        __syncthreads();
        if (tid == 0) {
            int r = s_rank; unsigned cum = 0; int bk = 0;
            for (; bk < 256; ++bk) {
                if (cum + hist[bk] > (unsigned)r) break;
                cum += hist[bk];
            }
            s_prefix = prefix | ((unsigned)bk << shift);
            s_rank   = r - (int)cum;
        }
        __syncthreads();
    }
    if (tid == 0) {
        int o = blockIdx.x & 3;
        float median  = __uint_as_float(s_prefix);
        float mean_e2 = median * 1.4426950408889634f;       // -median/ln(0.5)
        float tau = sqrtf(mean_e2 / g_em[o] * g_aiaj[o]);
        g_thr[blockIdx.x] = tau * 1.5079922765f;            // (c + 2d)/1.7
    }
}

// ---------------- pc map ----------------
__global__ void k_pc()
{
    unsigned idx = blockIdx.x * 256 + threadIdx.x;          // 32*HW
    size_t cn  = idx >> 16;
    size_t pix = idx & 65535;
    float a = 0.0f, acc = 0.0f;
    #pragma unroll
    for (int o = 0; o < 4; ++o) {
        size_t off = (cn*4 + o) * HW + pix;
        a   += g_amp4[off];
        acc += fmaxf(g_energy[off] - g_thr[cn*4 + o], 0.0f);
    }
    g_pc[idx] = acc / (a + 1e-8f);
}

// ---------------- FSIM pointwise + per-block reduction ----------------
__global__ void k_fsim_partial(const float* __restrict__ ker)
{
    const float T1 = 0.85f;
    const float T2 = 160.0f / 65025.0f;
    const float T3 = 200.0f / 65025.0f;
    const float T4 = 200.0f / 65025.0f;
    int tid = threadIdx.x;
    int n   = blockIdx.x >> 8;
    int pix = ((blockIdx.x & 255) << 8) | tid;
    int h = pix >> 8, w = pix & 255;

    const float* Yx = g_yiq + ((size_t)(0*NIMG + n) * 3 + 0) * HW;
    const float* Yy = g_yiq + ((size_t)(1*NIMG + n) * 3 + 0) * HW;

    float g0x = 0.f, g1x = 0.f, g0y = 0.f, g1y = 0.f;
    #pragma unroll
    for (int ky = 0; ky < 3; ++ky) {
        int hh = h + ky - 1;
        if (hh < 0 || hh > 255) continue;
        #pragma unroll
        for (int kx = 0; kx < 3; ++kx) {
            int ww = w + kx - 1;
            if (ww < 0 || ww > 255) continue;
            float vx = Yx[hh*256 + ww], vy = Yy[hh*256 + ww];
            float k0 = ker[ky*3 + kx], k1 = ker[9 + ky*3 + kx];
            g0x += k0*vx; g1x += k1*vx;
            g0y += k0*vy; g1y += k1*vy;
        }
    }
    float gX = sqrtf(g0x*g0x + g1x*g1x);
    float gY = sqrtf(g0y*g0y + g1y*g1y);

    float pcx = g_pc[(size_t)(0*NIMG + n) * HW + pix];
    float pcy = g_pc[(size_t)(1*NIMG + n) * HW + pix];
    float s_pc = (2.0f*pcx*pcy + T1) / (pcx*pcx + pcy*pcy + T1);
    float s_g  = (2.0f*gX*gY + T2) / (gX*gX + gY*gY + T2);

    float ix = g_yiq[((size_t)(0*NIMG + n) * 3 + 1) * HW + pix];
    float iy = g_yiq[((size_t)(1*NIMG + n) * 3 + 1) * HW + pix];
    float qx = g_yiq[((size_t)(0*NIMG + n) * 3 + 2) * HW + pix];
    float qy = g_yiq[((size_t)(1*NIMG + n) * 3 + 2) * HW + pix];
    float s_i = (2.0f*ix*iy + T3) / (ix*ix + iy*iy + T3);
    float s_q = (2.0f*qx*qy + T4) / (qx*qx + qy*qy + T4);
    float siq = s_i * s_q;
    float slam = __powf(fabsf(siq), 0.03f) * (siq < 0.0f ? 0.99556196f : 1.0f); // cos(0.03*pi)

    float pcm = fmaxf(pcx, pcy);
    float num = s_pc * s_g * slam * pcm;
    float den = pcm;

    __shared__ float sn[256], sd[256];
    sn[tid] = num; sd[tid] = den;
    __syncthreads();
    for (int s = 128; s > 0; s >>= 1) {
        if (tid < s) { sn[tid] += sn[tid + s]; sd[tid] += sd[tid + s]; }
        __syncthreads();
    }
    if (tid == 0) {
        g_part[blockIdx.x]        = sn[0];
        g_part[4096 + blockIdx.x] = sd[0];
    }
}

__global__ void k_final(float* __restrict__ out)
{
    int tid = threadIdx.x;          // 512
    int n = tid >> 5, lane = tid & 31;
    float num = 0.f, den = 0.f;
    for (int i = lane; i < 256; i += 32) {
        num += g_part[n*256 + i];
        den += g_part[4096 + n*256 + i];
    }
    #pragma unroll
    for (int off = 16; off > 0; off >>= 1) {
        num += __shfl_down_sync(0xffffffffu, num, off);
        den += __shfl_down_sync(0xffffffffu, den, off);
    }
    __shared__ float fs[16];
    if (lane == 0) fs[n] = num / den;
    __syncthreads();
    if (tid == 0) {
        float s = 0.f;
        #pragma unroll
        for (int k = 0; k < 16; ++k) s += fs[k];
        out[0] = s * (1.0f / 16.0f);
    }
}

// ---------------- launch ----------------
extern "C" void kernel_launch(void* const* d_in, const int* in_sizes, int n_in,
                              void* d_out, int out_size)
{
    (void)in_sizes; (void)n_in; (void)out_size;
    const float* x   = (const float*)d_in[0];
    const float* y   = (const float*)d_in[1];
    const float* ker = (const float*)d_in[2];
    float* out = (float*)d_out;

    k_twiddles         <<<1, 32>>>();
    k_preprocess       <<<4096, 256>>>(x, y);
    k_filters          <<<256, 256>>>();
    k_filter_stats     <<<4, 256>>>();
    k_fft_rows_fwd     <<<1024, 256>>>();
    k_fft_cols_fwd     <<<1024, 256>>>();
    k_ifft_cols_filt   <<<2048, 128>>>();
    k_ifft_rows_energy <<<8192, 128>>>();
    k_median           <<<128, 256>>>();
    k_pc               <<<8192, 256>>>();
    k_fsim_partial     <<<4096, 256>>>(ker);
    k_final            <<<1, 512>>>(out);
}